// round 9
// baseline (speedup 1.0000x reference)
#include <cuda_runtime.h>
#include <cuda_bf16.h>

#define BB 64
#define TT 288
#define VV 24
#define DD 256
#define NBT (BB * TT)
#define CHUNK 16                    // t per CTA; 288 % 16 == 0 -> b fixed per CTA
#define NXCTA (NBT / CHUNK)         // 1152
// float4 columns: 0..31 tod | 32..39 dow | 40..47 dom | 48..63 doy

__global__ __launch_bounds__(512, 4) void input_embedding_kernel(
    const float* __restrict__ features,     // (B,T,V)
    const int*   __restrict__ bar_in_day,   // (B,T)
    const int*   __restrict__ day_of_week,  // (B,)
    const int*   __restrict__ day_of_month, // (B,)
    const int*   __restrict__ day_of_year,  // (B,)
    const float4* __restrict__ W,           // (V,D) as float4
    const float4* __restrict__ bias,        // (V,D) as float4
    const float4* __restrict__ tod_table,   // (288,32) float4
    const float4* __restrict__ dow_table,   // (7,8)    float4
    const float4* __restrict__ dom_table,   // (32,8)   float4
    const float4* __restrict__ doy_table,   // (367,16) float4
    float4* __restrict__ out)               // (B,T,V,D) as float4
{
    const int tid = threadIdx.x;          // 0..511
    const int d4  = tid & 63;             // float4 column, fixed per thread
    const int v   = blockIdx.y * 8 + (tid >> 6);   // this thread's single variable row

    const int bt0 = blockIdx.x * CHUNK;
    const int b   = bt0 / TT;             // constant for the whole CTA

    // ---- this thread's entire W/bias working set: ONE float4 each ----
    const float4 w  = W[v * 64 + d4];
    const float4 bv = bias[v * 64 + d4];

    // ---- positional float4: segment fixed per thread; only tod varies with t ----
    float4 pp;
    if (d4 >= 48)      pp = doy_table[day_of_year[b] * 16 + (d4 - 48)];
    else if (d4 >= 40) pp = dom_table[day_of_month[b] * 8 + (d4 - 40)];
    else if (d4 >= 32) pp = dow_table[day_of_week[b] * 8 + (d4 - 32)];
    const bool is_tod = (d4 < 32);

    const float* __restrict__ fbase = features + bt0 * VV + v;
    float4* __restrict__ obase = out + (size_t)bt0 * (VV * DD / 4) + v * 64 + d4;

    #pragma unroll 4
    for (int i = 0; i < CHUNK; i++) {
        if (is_tod) pp = tod_table[bar_in_day[bt0 + i] * 32 + d4];  // half the warps
        const float x = __ldg(fbase + i * VV);                      // warp-uniform

        float4 o;
        o.x = fmaf(x, w.x, bv.x) + pp.x;
        o.y = fmaf(x, w.y, bv.y) + pp.y;
        o.z = fmaf(x, w.z, bv.z) + pp.z;
        o.w = fmaf(x, w.w, bv.w) + pp.w;
        __stcs(obase + i * (VV * DD / 4), o);   // streaming store
    }
}

extern "C" void kernel_launch(void* const* d_in, const int* in_sizes, int n_in,
                              void* d_out, int out_size) {
    const float* features     = (const float*)d_in[0];
    const int*   bar_in_day   = (const int*)d_in[1];
    const int*   day_of_week  = (const int*)d_in[2];
    const int*   day_of_month = (const int*)d_in[3];
    const int*   day_of_year  = (const int*)d_in[4];
    const float4* W           = (const float4*)d_in[5];
    const float4* bias        = (const float4*)d_in[6];
    const float4* tod_table   = (const float4*)d_in[7];
    const float4* dow_table   = (const float4*)d_in[8];
    const float4* dom_table   = (const float4*)d_in[9];
    const float4* doy_table   = (const float4*)d_in[10];
    float4* out = (float4*)d_out;

    dim3 grid(NXCTA, 3);   // y: three 8-row v-octaves
    input_embedding_kernel<<<grid, 512>>>(
        features, bar_in_day, day_of_week, day_of_month, day_of_year,
        W, bias, tod_table, dow_table, dom_table, doy_table, out);
}

// round 10
// speedup vs baseline: 1.4787x; 1.4787x over previous
#include <cuda_runtime.h>
#include <cuda_bf16.h>

#define BB 64
#define TT 288
#define VV 24
#define DD 256
// TOD 128 | DOW 32 | DOM 32 | DOY 64

__global__ __launch_bounds__(256, 8) void input_embedding_kernel(
    const float* __restrict__ features,     // (B,T,V)
    const int*   __restrict__ bar_in_day,   // (B,T)
    const int*   __restrict__ day_of_week,  // (B,)
    const int*   __restrict__ day_of_month, // (B,)
    const int*   __restrict__ day_of_year,  // (B,)
    const float4* __restrict__ W,           // (V,D) as float4
    const float4* __restrict__ bias,        // (V,D) as float4
    const float* __restrict__ tod_table,    // (288,128)
    const float* __restrict__ dow_table,    // (7,32)
    const float* __restrict__ dom_table,    // (32,32)
    const float* __restrict__ doy_table,    // (367,64)
    float4* __restrict__ out)               // (B,T,V,D) as float4
{
    __shared__ __align__(16) float pos[DD];
    __shared__ float sx[VV];

    const int bt  = blockIdx.x;       // b*T + t
    const int b   = bt / TT;
    const int tid = threadIdx.x;

    // ---- build composite positional vector pos[0..255] in smem ----
    if (tid < 128) {
        const int tod = bar_in_day[bt];
        pos[tid] = tod_table[tod * 128 + tid];
    } else if (tid < 160) {
        pos[tid] = dow_table[day_of_week[b] * 32 + (tid - 128)];
    } else if (tid < 192) {
        pos[tid] = dom_table[day_of_month[b] * 32 + (tid - 160)];
    } else {
        pos[tid] = doy_table[day_of_year[b] * 64 + (tid - 192)];
    }
    if (tid < VV) sx[tid] = features[bt * VV + tid];
    __syncthreads();

    const float4* __restrict__ pos4 = reinterpret_cast<const float4*>(pos);
    float4* __restrict__ outb = out + (size_t)bt * (VV * DD / 4);

    // 24 rows of 64 float4 = 1536 float4 per block; 6 per thread.
    // NOTE: the per-iteration sx/W/bias/pos4 loads are deliberate — they
    // interleave independent work between the .cs stores and sustain the
    // write stream (hoisting them regressed in R5; register-caching in
    // R2/R3/R9; wider stores in R6).
    #pragma unroll
    for (int k = 0; k < 6; k++) {
        const int p  = tid + k * 256;   // 0..1535
        const int v  = p >> 6;          // uniform across each warp
        const int d4 = p & 63;
        const float  x  = sx[v];
        const float4 w  = W[v * 64 + d4];
        const float4 bv = bias[v * 64 + d4];
        const float4 pp = pos4[d4];
        float4 o;
        o.x = fmaf(x, w.x, bv.x) + pp.x;
        o.y = fmaf(x, w.y, bv.y) + pp.y;
        o.z = fmaf(x, w.z, bv.z) + pp.z;
        o.w = fmaf(x, w.w, bv.w) + pp.w;
        __stcs(&outb[p], o);            // streaming store: keep output out of L2
    }
}

extern "C" void kernel_launch(void* const* d_in, const int* in_sizes, int n_in,
                              void* d_out, int out_size) {
    const float* features     = (const float*)d_in[0];
    const int*   bar_in_day   = (const int*)d_in[1];
    const int*   day_of_week  = (const int*)d_in[2];
    const int*   day_of_month = (const int*)d_in[3];
    const int*   day_of_year  = (const int*)d_in[4];
    const float4* W           = (const float4*)d_in[5];
    const float4* bias        = (const float4*)d_in[6];
    const float* tod_table    = (const float*)d_in[7];
    const float* dow_table    = (const float*)d_in[8];
    const float* dom_table    = (const float*)d_in[9];
    const float* doy_table    = (const float*)d_in[10];
    float4* out = (float4*)d_out;

    input_embedding_kernel<<<BB * TT, 256>>>(
        features, bar_in_day, day_of_week, day_of_month, day_of_year,
        W, bias, tod_table, dow_table, dom_table, doy_table, out);
}